// round 7
// baseline (speedup 1.0000x reference)
#include <cuda_runtime.h>

// Problem constants
#define NB    32
#define NH    12
#define GRID  14          // GH == GW
#define LTOK  196         // GRID*GRID
#define DHEAD 64
#define NSTEP 13          // steps 1..13
#define CHUNK 32          // d-chunk per block (DHEAD/2)
#define NPAIR 16          // d-pairs per block
#define TPB   224         // 14 lines x 16 d-pairs = 224, one task/thread/phase

// out[b,h,m,d] = x[b,h,m,d]
//   + sum_{dir,step valid} C[h][dir][step][d] * x[b,h,neighbor(m,dir,step),d]
// C[h][dir][step][d] = sd(step)*P[dir*4+si][d][h] + nd(step)*P[dir*4+si+1][d][h],
// P = param_1 + param_2.  Separable: ys = x + V(x) in smem, out = ys + H(x).
// Hot loops use packed fma.rn.f32x2 (FFMA2): each thread owns a d-PAIR.
//
// Step tables (precomputed, matches reference double-precision build to ~1e-7):
__constant__ float DIST_C[NSTEP] = {
    0.9949110f, 0.9797987f, 0.9551199f, 0.9216104f, 0.8802485f,
    0.8322075f, 0.7788008f, 0.7214223f, 0.6614868f, 0.6003730f,
    0.5393734f, 0.4796523f, 0.4222132f };
__constant__ float FRAC_C[NSTEP] = {
    0.00000000f, 0.23076923f, 0.46153846f, 0.69230769f, 0.92307692f,
    0.15384615f, 0.38461538f, 0.61538462f, 0.84615385f, 0.07692308f,
    0.30769231f, 0.53846154f, 0.76923077f };
__constant__ int SI_C[NSTEP] = { 0,0,0,0,0, 1,1,1,1, 2,2,2,2 };

typedef unsigned long long u64;

__device__ __forceinline__ u64 ffma2(u64 a, u64 b, u64 c) {
    u64 d;
    asm("fma.rn.f32x2 %0, %1, %2, %3;" : "=l"(d) : "l"(a), "l"(b), "l"(c));
    return d;
}

__global__ __launch_bounds__(TPB, 4)
void save_kernel(const float* __restrict__ x,
                 const float* __restrict__ p1,
                 const float* __restrict__ p2,
                 float* __restrict__ out)
{
    __shared__ float xs[LTOK * CHUNK];           // 25088 B : x tile (d-half)
    __shared__ float ys[LTOK * CHUNK];           // 25088 B : x + V(x)
    __shared__ float Cs[4 * NSTEP * CHUNK];      //  6656 B : per-(head,d) coeffs

    const int blk = blockIdx.x;       // (b*NH + h) * 2 + dhalf
    const int bh  = blk >> 1;
    const int dlo = (blk & 1) * CHUNK;
    const int hd  = bh % NH;
    const int tid = threadIdx.x;

    const float* xb = x   + (size_t)bh * (LTOK * DHEAD);
    float*       ob = out + (size_t)bh * (LTOK * DHEAD);

    // ---- load x tile (d-half) into smem, float4-vectorized ----
    {
        const float4* x4  = (const float4*)(xb + dlo);
        float4*       xs4 = (float4*)xs;
        #pragma unroll
        for (int it = 0; it < (LTOK * (CHUNK / 4)) / TPB; it++) {
            int i   = tid + it * TPB;
            int row = i >> 3;
            int c4  = i & 7;
            xs4[i] = x4[row * (DHEAD / 4) + c4];
        }
    }

    // ---- build coefficients Cs[dir][step][d_local] ----
    // param layout: p[(k*DHEAD + d)*NH + h]
    #pragma unroll
    for (int it = 0; it < 8; it++) {
        int i = tid + it * TPB;
        if (i < 4 * NSTEP * CHUNK) {
            int d    = i & (CHUNK - 1);
            int sidx = (i >> 5) % NSTEP;
            int dir  = i / (NSTEP * CHUNK);
            int si   = SI_C[sidx];
            float fr = FRAC_C[sidx];
            float ds = DIST_C[sidx];
            int k0   = dir * 4 + si;
            int ia   = (k0 * DHEAD + dlo + d) * NH + hd;
            int ib   = ((k0 + 1) * DHEAD + dlo + d) * NH + hd;
            float pa = p1[ia] + p2[ia];
            float pb = p1[ib] + p2[ib];
            Cs[i] = ds * (1.0f - fr) * pa + ds * fr * pb;
        }
    }
    __syncthreads();

    const int dp = (tid & (NPAIR - 1)) * 2;   // d-pair base within chunk
    const int g0 = tid >> 4;                  // line index 0..13

    // ===== V phase: ys = x + vertical conv, packed f32x2 =====
    {
        const int w = g0;

        u64 xc[GRID], acc[GRID];
        #pragma unroll
        for (int hh = 0; hh < GRID; hh++) {
            xc[hh]  = *(const u64*)&xs[(hh * GRID + w) * CHUNK + dp];
            acc[hh] = xc[hh];
        }
        #pragma unroll
        for (int s = 1; s <= NSTEP; s++) {
            u64 c0 = *(const u64*)&Cs[(0 * NSTEP + (s - 1)) * CHUNK + dp]; // top
            u64 c1 = *(const u64*)&Cs[(1 * NSTEP + (s - 1)) * CHUNK + dp]; // bottom
            #pragma unroll
            for (int hh = s; hh < GRID; hh++)
                acc[hh] = ffma2(c0, xc[hh - s], acc[hh]);
            #pragma unroll
            for (int hh = 0; hh + s < GRID; hh++)
                acc[hh] = ffma2(c1, xc[hh + s], acc[hh]);
        }
        #pragma unroll
        for (int hh = 0; hh < GRID; hh++)
            *(u64*)&ys[(hh * GRID + w) * CHUNK + dp] = acc[hh];
    }
    __syncthreads();   // ys complete before H-phase reads

    // ===== H phase: out = ys + horizontal conv, packed f32x2 =====
    {
        const int hr = g0;

        u64 xr[GRID], acc[GRID];
        #pragma unroll
        for (int ww = 0; ww < GRID; ww++) {
            xr[ww]  = *(const u64*)&xs[(hr * GRID + ww) * CHUNK + dp];
            acc[ww] = *(const u64*)&ys[(hr * GRID + ww) * CHUNK + dp]; // x + V in
        }
        #pragma unroll
        for (int s = 1; s <= NSTEP; s++) {
            u64 c2 = *(const u64*)&Cs[(2 * NSTEP + (s - 1)) * CHUNK + dp]; // left
            u64 c3 = *(const u64*)&Cs[(3 * NSTEP + (s - 1)) * CHUNK + dp]; // right
            #pragma unroll
            for (int ww = s; ww < GRID; ww++)
                acc[ww] = ffma2(c2, xr[ww - s], acc[ww]);
            #pragma unroll
            for (int ww = 0; ww + s < GRID; ww++)
                acc[ww] = ffma2(c3, xr[ww + s], acc[ww]);
        }
        #pragma unroll
        for (int ww = 0; ww < GRID; ww++)
            *(u64*)&ob[(hr * GRID + ww) * DHEAD + dlo + dp] = acc[ww];
    }
}

extern "C" void kernel_launch(void* const* d_in, const int* in_sizes, int n_in,
                              void* d_out, int out_size)
{
    // metadata order: x, table, param_1, param_2 (table recomputed analytically)
    const float* x  = (const float*)d_in[0];
    const float* p1 = (const float*)d_in[2];
    const float* p2 = (const float*)d_in[3];
    float*       out = (float*)d_out;

    save_kernel<<<NB * NH * 2, TPB>>>(x, p1, p2, out);
}